// round 6
// baseline (speedup 1.0000x reference)
#include <cuda_runtime.h>
#include <math.h>

#define CDIV(a,b) (((a)+(b)-1)/(b))

static constexpr int BB   = 32;
static constexpr int CINN = 128;
static constexpr int CO   = 256;
static constexpr int HWP  = 1024;          // 32*32
static constexpr int MTOT = BB * HWP;      // 32768
static constexpr int MEMN = 64;

// ---------------- scratch (static device memory; no allocations) ----------------
__device__ float g_xT   [(size_t)CINN * MTOT];        // x transposed  [128][M]
__device__ float g_col  [(size_t)2304 * MTOT];        // im2col buffer [K][M]
__device__ float g_t1   [(size_t)CO * MTOT];          // conv1 raw     [256][M]
__device__ float g_t2   [(size_t)CO * MTOT];          // conv2 raw
__device__ float g_id   [(size_t)CO * MTOT];          // shortcut conv raw
__device__ float g_h    [(size_t)CO * MTOT];          // ctrl hidden
__device__ float g_q    [(size_t)CO * MTOT];          // ctrl out (query)
__device__ float g_xfret[(size_t)512 * MTOT];         // [xfT(256) ; retT(256)][M]
__device__ float g_attn [(size_t)MEMN * MTOT];        // attn transposed [64][M]
__device__ float g_mo   [(size_t)CO * MTOT];          // memory out
__device__ float g_memT [CO * MEMN];                  // mem transposed [256][64]
__device__ float4 g_stats1 [CO * BB];
__device__ float4 g_stats2 [CO * BB];
__device__ float4 g_statsid[CO * BB];
__device__ float g_a1[CO], g_c1[CO], g_a2[CO], g_c2[CO], g_asc[CO], g_csc[CO];
__device__ float g_chatt[BB * CO];
__device__ float g_spmean[MTOT], g_spmax[MTOT], g_sa[MTOT];

// ---------------- transpose x: NCHW -> [ci][b*1024+p] ----------------
__global__ void k_transpose_x(const float* __restrict__ x) {
    int id = blockIdx.x * 256 + threadIdx.x;      // 32*128*1024 total
    float v = x[id];
    int p  = id & 1023;
    int ci = (id >> 10) & 127;
    int b  = id >> 17;
    g_xT[(size_t)ci * MTOT + b * HWP + p] = v;
}

// ---------------- im2col (T layout both sides), optional fused BN+ReLU ----------------
__global__ void k_im2col(const float* __restrict__ src, float* __restrict__ dst,
                         const float* __restrict__ aa, const float* __restrict__ cc,
                         int doAct) {
    int k  = blockIdx.y;               // ci*9 + r
    int ci = k / 9, r = k % 9;
    int dh = r / 3 - 1, dw = r % 3 - 1;
    int m  = blockIdx.x * 256 + threadIdx.x;
    int p  = m & 1023, b = m >> 10;
    int h  = (p >> 5) + dh, w = (p & 31) + dw;
    float v = 0.f;
    if ((unsigned)h < 32u && (unsigned)w < 32u) {
        v = src[(size_t)ci * MTOT + b * HWP + h * 32 + w];
        if (doAct) v = fmaxf(fmaf(aa[ci], v, cc[ci]), 0.f);
    }
    dst[(size_t)k * MTOT + m] = v;
}

// ---------------- generic GEMM: C[n][m] = sum_k A[k][m]*B[n][k] (+bias, epilogue) ----
// EPI: 0 = bias, 1 = bias+relu, 2 = gate epilogue (sigmoid(acc+bias); blend ret/xf)
template <int EPI>
__global__ void __launch_bounds__(256, 2)
k_gemm(const float* __restrict__ A, const float* __restrict__ Bw,
       const float* __restrict__ bias, float* __restrict__ C, int K,
       const float* __restrict__ e_xf, const float* __restrict__ e_ret) {
    __shared__ float As[16][128];
    __shared__ float Bs[16][128];
    int tid = threadIdx.x;
    int m0 = blockIdx.x * 128, n0 = blockIdx.y * 128;
    float acc[8][8];
#pragma unroll
    for (int i = 0; i < 8; i++)
#pragma unroll
        for (int j = 0; j < 8; j++) acc[i][j] = 0.f;

    int m4 = tid & 31, kr = tid >> 5;        // A loader
    int nn = tid & 127, kq = tid >> 7;       // B loader
    int tx = tid & 15, ty = tid >> 4;        // compute map

    for (int k0 = 0; k0 < K; k0 += 16) {
#pragma unroll
        for (int s = 0; s < 2; s++) {
            int kk = kr + s * 8;
            *(float4*)&As[kk][m4 * 4] =
                *(const float4*)&A[(size_t)(k0 + kk) * MTOT + m0 + m4 * 4];
        }
#pragma unroll
        for (int s = 0; s < 2; s++) {
            int kq2 = kq + s * 2;
            float4 v = *(const float4*)&Bw[(size_t)(n0 + nn) * K + k0 + kq2 * 4];
            Bs[kq2 * 4 + 0][nn] = v.x; Bs[kq2 * 4 + 1][nn] = v.y;
            Bs[kq2 * 4 + 2][nn] = v.z; Bs[kq2 * 4 + 3][nn] = v.w;
        }
        __syncthreads();
#pragma unroll
        for (int kk = 0; kk < 16; kk++) {
            float a[8], b[8];
#pragma unroll
            for (int i = 0; i < 8; i++) a[i] = As[kk][ty * 8 + i];
#pragma unroll
            for (int j = 0; j < 8; j++) b[j] = Bs[kk][tx * 8 + j];
#pragma unroll
            for (int i = 0; i < 8; i++)
#pragma unroll
                for (int j = 0; j < 8; j++) acc[i][j] = fmaf(a[i], b[j], acc[i][j]);
        }
        __syncthreads();
    }
#pragma unroll
    for (int j = 0; j < 8; j++) {
        int n = n0 + tx * 8 + j;
        float bv = bias ? bias[n] : 0.f;
#pragma unroll
        for (int i = 0; i < 8; i++) {
            int m = m0 + ty * 8 + i;
            float v = acc[i][j] + bv;
            if (EPI == 1) v = fmaxf(v, 0.f);
            if (EPI == 2) {
                float g = 1.f / (1.f + expf(-v));
                size_t off = (size_t)n * MTOT + m;
                v = g * e_ret[off] + (1.f - g) * e_xf[off];
            }
            C[(size_t)n * MTOT + m] = v;
        }
    }
}

// ---------------- per-(c,b) reduction: sum, sumsq, max, min over 1024 ----------------
__global__ void __launch_bounds__(256) k_reduce_bc(const float* __restrict__ src,
                                                   float4* __restrict__ out) {
    int cb = blockIdx.x;                      // = c*32 + b  (layout makes this contiguous)
    const float* p = src + (size_t)cb * HWP;
    int tid = threadIdx.x;
    float v0 = p[tid], v1 = p[tid + 256], v2 = p[tid + 512], v3 = p[tid + 768];
    float s  = v0 + v1 + v2 + v3;
    float ss = v0 * v0 + v1 * v1 + v2 * v2 + v3 * v3;
    float mx = fmaxf(fmaxf(v0, v1), fmaxf(v2, v3));
    float mn = fminf(fminf(v0, v1), fminf(v2, v3));
#pragma unroll
    for (int o = 16; o; o >>= 1) {
        s  += __shfl_down_sync(0xffffffffu, s, o);
        ss += __shfl_down_sync(0xffffffffu, ss, o);
        mx = fmaxf(mx, __shfl_down_sync(0xffffffffu, mx, o));
        mn = fminf(mn, __shfl_down_sync(0xffffffffu, mn, o));
    }
    __shared__ float4 wred[8];
    int lane = tid & 31, wid = tid >> 5;
    if (lane == 0) wred[wid] = make_float4(s, ss, mx, mn);
    __syncthreads();
    if (tid == 0) {
        float4 r = wred[0];
        for (int i = 1; i < 8; i++) {
            r.x += wred[i].x; r.y += wred[i].y;
            r.z = fmaxf(r.z, wred[i].z); r.w = fminf(r.w, wred[i].w);
        }
        out[cb] = r;
    }
}

// ---------------- finalize BN coefficients per channel ----------------
__global__ void k_bn_coeffs(const float4* __restrict__ stats,
                            const float* __restrict__ g, const float* __restrict__ beta,
                            float* __restrict__ a, float* __restrict__ c) {
    int ch = threadIdx.x;     // <<<1,256>>>
    float s = 0.f, ss = 0.f;
    for (int b = 0; b < BB; b++) { float4 v = stats[ch * BB + b]; s += v.x; ss += v.y; }
    float mean = s * (1.f / 32768.f);
    float var  = ss * (1.f / 32768.f) - mean * mean;
    float av = g[ch] * rsqrtf(var + 1e-5f);
    a[ch] = av;
    c[ch] = beta[ch] - av * mean;
}

// ---------------- channel attention MLP ----------------
__global__ void __launch_bounds__(256) k_ca_mlp(const float* __restrict__ w1,
                                                const float* __restrict__ w2) {
    int b = blockIdx.x, tid = threadIdx.x;
    __shared__ float va[CO], vm[CO], hsum[16];
    {
        float4 st = g_stats2[tid * BB + b];
        float a = g_a2[tid], c = g_c2[tid];
        va[tid] = a * st.x * (1.f / 1024.f) + c;
        vm[tid] = (a >= 0.f ? a * st.z : a * st.w) + c;
    }
    __syncthreads();
    int wid = tid >> 5, lane = tid & 31;
    for (int u = 0; u < 2; u++) {
        int j = wid * 2 + u;
        float sa = 0.f, sm = 0.f;
        for (int c = lane; c < CO; c += 32) {
            float wv = w1[j * CO + c];
            sa += wv * va[c]; sm += wv * vm[c];
        }
#pragma unroll
        for (int o = 16; o; o >>= 1) {
            sa += __shfl_down_sync(0xffffffffu, sa, o);
            sm += __shfl_down_sync(0xffffffffu, sm, o);
        }
        if (lane == 0) hsum[j] = fmaxf(sa, 0.f) + fmaxf(sm, 0.f);
    }
    __syncthreads();
    float s = 0.f;
    for (int j = 0; j < 16; j++) s += hsum[j] * w2[tid * 16 + j];
    g_chatt[b * CO + tid] = 1.f / (1.f + expf(-s));
}

// ---------------- spatial pooling over channels (mean & max) ----------------
__global__ void __launch_bounds__(256) k_sp_pool() {
    int m = blockIdx.x * 256 + threadIdx.x;
    int b = m >> 10;
    __shared__ float co[CO], of[CO];
    {
        int t = threadIdx.x;
        float ca = g_chatt[b * CO + t];
        co[t] = ca * g_a2[t];
        of[t] = ca * g_c2[t];
    }
    __syncthreads();
    float s = 0.f, mx = -1e30f;
    for (int c = 0; c < CO; c++) {
        float v = fmaf(co[c], g_t2[(size_t)c * MTOT + m], of[c]);
        s += v; mx = fmaxf(mx, v);
    }
    g_spmean[m] = s * (1.f / 256.f);
    g_spmax[m]  = mx;
}

// ---------------- spatial attention 7x7 conv + sigmoid ----------------
__global__ void __launch_bounds__(1024) k_sa_conv(const float* __restrict__ sw,
                                                  const float* __restrict__ sb) {
    int b = blockIdx.x, p = threadIdx.x;
    __shared__ float me[HWP], ma[HWP];
    me[p] = g_spmean[b * HWP + p];
    ma[p] = g_spmax[b * HWP + p];
    __syncthreads();
    int h = p >> 5, w = p & 31;
    float acc = sb[0];
#pragma unroll
    for (int kh = 0; kh < 7; kh++) {
        int hh = h + kh - 3;
        if ((unsigned)hh >= 32u) continue;
#pragma unroll
        for (int kw = 0; kw < 7; kw++) {
            int ww = w + kw - 3;
            if ((unsigned)ww >= 32u) continue;
            int q = hh * 32 + ww;
            acc += sw[kh * 7 + kw] * me[q] + sw[49 + kh * 7 + kw] * ma[q];
        }
    }
    g_sa[b * HWP + p] = 1.f / (1.f + expf(-acc));
}

// ---------------- build xf (post channel+spatial attention), T layout ----------------
__global__ void k_build_xf() {
    int c = blockIdx.y;
    int m = blockIdx.x * 256 + threadIdx.x;
    int b = m >> 10;
    float ca = g_chatt[b * CO + c];
    float v = ca * fmaf(g_a2[c], g_t2[(size_t)c * MTOT + m], g_c2[c]) * g_sa[m];
    g_xfret[(size_t)c * MTOT + m] = v;
}

// ---------------- mem transpose [64][256] -> [256][64] ----------------
__global__ void k_mem_t(const float* __restrict__ mem) {
    int id = blockIdx.x * 256 + threadIdx.x;   // 16384
    int j = id >> 8, n = id & 255;
    g_memT[n * MEMN + j] = mem[id];
}

// ---------------- logits + softmax (rows of 64), writes attnT [64][M] ----------------
__global__ void __launch_bounds__(256) k_logits_softmax(const float* __restrict__ keys) {
    __shared__ float qs[16][128];
    __shared__ float ks[16][64];
    __shared__ float red[128][8];
    __shared__ float rowred[128];
    int tid = threadIdx.x;
    int m0 = blockIdx.x * 128;
    float acc[4][8];
#pragma unroll
    for (int i = 0; i < 4; i++)
#pragma unroll
        for (int j = 0; j < 8; j++) acc[i][j] = 0.f;
    int m4 = tid & 31, kr = tid >> 5;
    int jb = tid & 63, kq = tid >> 6;
    int tx = tid & 7, ty = tid >> 3;
    for (int k0 = 0; k0 < 256; k0 += 16) {
#pragma unroll
        for (int s = 0; s < 2; s++) {
            int kk = kr + s * 8;
            *(float4*)&qs[kk][m4 * 4] =
                *(const float4*)&g_q[(size_t)(k0 + kk) * MTOT + m0 + m4 * 4];
        }
        {
            float4 v = *(const float4*)&keys[jb * 256 + k0 + kq * 4];
            ks[kq * 4 + 0][jb] = v.x; ks[kq * 4 + 1][jb] = v.y;
            ks[kq * 4 + 2][jb] = v.z; ks[kq * 4 + 3][jb] = v.w;
        }
        __syncthreads();
#pragma unroll
        for (int kk = 0; kk < 16; kk++) {
            float a[4], b[8];
#pragma unroll
            for (int i = 0; i < 4; i++) a[i] = qs[kk][ty * 4 + i];
#pragma unroll
            for (int j = 0; j < 8; j++) b[j] = ks[kk][tx * 8 + j];
#pragma unroll
            for (int i = 0; i < 4; i++)
#pragma unroll
                for (int j = 0; j < 8; j++) acc[i][j] = fmaf(a[i], b[j], acc[i][j]);
        }
        __syncthreads();
    }
    const float sc = 0.0625f;   // 1/sqrt(256)
#pragma unroll
    for (int i = 0; i < 4; i++) {
        float mx = -1e30f;
#pragma unroll
        for (int j = 0; j < 8; j++) { acc[i][j] *= sc; mx = fmaxf(mx, acc[i][j]); }
        red[ty * 4 + i][tx] = mx;
    }
    __syncthreads();
    if (tid < 128) {
        float mx = -1e30f;
        for (int t = 0; t < 8; t++) mx = fmaxf(mx, red[tid][t]);
        rowred[tid] = mx;
    }
    __syncthreads();
#pragma unroll
    for (int i = 0; i < 4; i++) {
        float rm = rowred[ty * 4 + i], s = 0.f;
#pragma unroll
        for (int j = 0; j < 8; j++) { acc[i][j] = expf(acc[i][j] - rm); s += acc[i][j]; }
        red[ty * 4 + i][tx] = s;
    }
    __syncthreads();
    if (tid < 128) {
        float s = 0.f;
        for (int t = 0; t < 8; t++) s += red[tid][t];
        rowred[tid] = 1.f / s;
    }
    __syncthreads();
#pragma unroll
    for (int i = 0; i < 4; i++) {
        float inv = rowred[ty * 4 + i];
#pragma unroll
        for (int j = 0; j < 8; j++)
            g_attn[(size_t)(tx * 8 + j) * MTOT + m0 + ty * 4 + i] = acc[i][j] * inv;
    }
}

// ---------------- final: spike + BN(shortcut) + relu, write NCHW ----------------
__global__ void k_final(float* __restrict__ out) {
    int c = blockIdx.y;
    int m = blockIdx.x * 256 + threadIdx.x;
    float mo = g_mo[(size_t)c * MTOT + m];
    float spike = (0.1f * mo >= 1.0f) ? 1.f : 0.f;
    float idv = fmaf(g_asc[c], g_id[(size_t)c * MTOT + m], g_csc[c]);
    int b = m >> 10, p = m & 1023;
    out[(size_t)b * CO * HWP + c * HWP + p] = fmaxf(spike + idv, 0.f);
}

// =============================== host launcher ===============================
extern "C" void kernel_launch(void* const* d_in, const int* in_sizes, int n_in,
                              void* d_out, int out_size) {
    const float* x       = (const float*)d_in[0];
    const float* conv1_w = (const float*)d_in[1];
    const float* conv1_b = (const float*)d_in[2];
    const float* bn1_g   = (const float*)d_in[3];
    const float* bn1_b   = (const float*)d_in[4];
    const float* conv2_w = (const float*)d_in[5];
    const float* conv2_b = (const float*)d_in[6];
    const float* bn2_g   = (const float*)d_in[7];
    const float* bn2_b   = (const float*)d_in[8];
    const float* ca_w1   = (const float*)d_in[9];
    const float* ca_w2   = (const float*)d_in[10];
    const float* sa_w    = (const float*)d_in[11];
    const float* sa_b    = (const float*)d_in[12];
    const float* memp    = (const float*)d_in[13];
    const float* mem_keys= (const float*)d_in[14];
    const float* ctrl_w1 = (const float*)d_in[15];
    const float* ctrl_b1 = (const float*)d_in[16];
    const float* ctrl_w2 = (const float*)d_in[17];
    const float* ctrl_b2 = (const float*)d_in[18];
    const float* gate_w  = (const float*)d_in[19];
    const float* gate_b  = (const float*)d_in[20];
    const float* sc_w    = (const float*)d_in[21];
    const float* sc_g    = (const float*)d_in[22];
    const float* sc_b    = (const float*)d_in[23];

    float *xT, *col, *t1, *t2, *idb, *hb, *qb, *xfret, *attn, *mo, *memT;
    float *a1, *c1, *a2, *c2, *asc, *csc;
    float4 *st1, *st2, *stid;
    cudaGetSymbolAddress((void**)&xT, g_xT);
    cudaGetSymbolAddress((void**)&col, g_col);
    cudaGetSymbolAddress((void**)&t1, g_t1);
    cudaGetSymbolAddress((void**)&t2, g_t2);
    cudaGetSymbolAddress((void**)&idb, g_id);
    cudaGetSymbolAddress((void**)&hb, g_h);
    cudaGetSymbolAddress((void**)&qb, g_q);
    cudaGetSymbolAddress((void**)&xfret, g_xfret);
    cudaGetSymbolAddress((void**)&attn, g_attn);
    cudaGetSymbolAddress((void**)&mo, g_mo);
    cudaGetSymbolAddress((void**)&memT, g_memT);
    cudaGetSymbolAddress((void**)&a1, g_a1);
    cudaGetSymbolAddress((void**)&c1, g_c1);
    cudaGetSymbolAddress((void**)&a2, g_a2);
    cudaGetSymbolAddress((void**)&c2, g_c2);
    cudaGetSymbolAddress((void**)&asc, g_asc);
    cudaGetSymbolAddress((void**)&csc, g_csc);
    cudaGetSymbolAddress((void**)&st1, g_stats1);
    cudaGetSymbolAddress((void**)&st2, g_stats2);
    cudaGetSymbolAddress((void**)&stid, g_statsid);

    dim3 gemm_grid(MTOT / 128, 2);   // N = 256 always

    // 1) transpose input
    k_transpose_x<<<BB * CINN * HWP / 256, 256>>>(x);

    // 2) shortcut conv (1x1): plain GEMM K=128
    k_gemm<0><<<gemm_grid, 256>>>(xT, sc_w, nullptr, idb, 128, nullptr, nullptr);
    k_reduce_bc<<<CO * BB, 256>>>(idb, stid);
    k_bn_coeffs<<<1, 256>>>(stid, sc_g, sc_b, asc, csc);

    // 3) conv1 = im2col + GEMM (K=1152)
    k_im2col<<<dim3(MTOT / 256, CINN * 9), 256>>>(xT, col, nullptr, nullptr, 0);
    k_gemm<0><<<gemm_grid, 256>>>(col, conv1_w, conv1_b, t1, CINN * 9, nullptr, nullptr);
    k_reduce_bc<<<CO * BB, 256>>>(t1, st1);
    k_bn_coeffs<<<1, 256>>>(st1, bn1_g, bn1_b, a1, c1);

    // 4) conv2 = im2col (fused BN1+relu) + GEMM (K=2304)
    k_im2col<<<dim3(MTOT / 256, CO * 9), 256>>>(t1, col, a1, c1, 1);
    k_gemm<0><<<gemm_grid, 256>>>(col, conv2_w, conv2_b, t2, CO * 9, nullptr, nullptr);
    k_reduce_bc<<<CO * BB, 256>>>(t2, st2);
    k_bn_coeffs<<<1, 256>>>(st2, bn2_g, bn2_b, a2, c2);

    // 5) channel attention (uses per-(b,c) stats of t2)
    k_ca_mlp<<<BB, 256>>>(ca_w1, ca_w2);

    // 6) spatial attention
    k_sp_pool<<<MTOT / 256, 256>>>();
    k_sa_conv<<<BB, 1024>>>(sa_w, sa_b);

    // 7) xf (attention-applied features) into front half of xfret buffer
    k_build_xf<<<dim3(MTOT / 256, CO), 256>>>();

    // 8) memory module
    k_gemm<1><<<gemm_grid, 256>>>(xfret, ctrl_w1, ctrl_b1, hb, 256, nullptr, nullptr);
    k_gemm<0><<<gemm_grid, 256>>>(hb, ctrl_w2, ctrl_b2, qb, 256, nullptr, nullptr);
    k_mem_t<<<MEMN * CO / 256, 256>>>(memp);
    k_logits_softmax<<<MTOT / 128, 256>>>(mem_keys);
    k_gemm<0><<<gemm_grid, 256>>>(attn, memT, nullptr, xfret + (size_t)256 * MTOT,
                                  MEMN, nullptr, nullptr);
    k_gemm<2><<<gemm_grid, 256>>>(xfret, gate_w, gate_b, mo, 512,
                                  xfret, xfret + (size_t)256 * MTOT);

    // 9) spike + shortcut + relu -> NCHW output
    k_final<<<dim3(MTOT / 256, CO), 256>>>((float*)d_out);
}

// round 7
// speedup vs baseline: 1.2926x; 1.2926x over previous
#include <cuda_runtime.h>
#include <math.h>
#include <stdint.h>

#define CDIV(a,b) (((a)+(b)-1)/(b))

static constexpr int BB   = 32;
static constexpr int CINN = 128;
static constexpr int CO   = 256;
static constexpr int HWP  = 1024;          // 32*32
static constexpr int MTOT = BB * HWP;      // 32768
static constexpr int MEMN = 64;

// ---------------- scratch (static device memory; no allocations) ----------------
__device__ float g_xT   [(size_t)CINN * MTOT];        // x transposed  [128][M]
__device__ float g_col  [(size_t)2304 * MTOT];        // im2col buffer [K][M]
__device__ float g_t1   [(size_t)CO * MTOT];          // conv1 raw     [256][M]
__device__ float g_t2   [(size_t)CO * MTOT];          // conv2 raw
__device__ float g_id   [(size_t)CO * MTOT];          // shortcut conv raw
__device__ float g_h    [(size_t)CO * MTOT];          // ctrl hidden
__device__ float g_q    [(size_t)CO * MTOT];          // ctrl out (query)
__device__ float g_xfret[(size_t)512 * MTOT];         // [xfT(256) ; retT(256)][M]
__device__ float g_attn [(size_t)MEMN * MTOT];        // attn transposed [64][M]
__device__ float g_mo   [(size_t)CO * MTOT];          // memory out
__device__ float g_memT [CO * MEMN];                  // mem transposed [256][64]
__device__ float4 g_stats1 [CO * BB];
__device__ float4 g_stats2 [CO * BB];
__device__ float4 g_statsid[CO * BB];
__device__ float g_a1[CO], g_c1[CO], g_a2[CO], g_c2[CO], g_asc[CO], g_csc[CO];
__device__ float g_chatt[BB * CO];
__device__ float g_spmean[MTOT], g_spmax[MTOT], g_sa[MTOT];

// ---------------- tf32 helpers ----------------
__device__ __forceinline__ void cvt_hilo(float x, uint32_t& h, uint32_t& l) {
    uint32_t hb;
    asm("cvt.rna.tf32.f32 %0, %1;" : "=r"(hb) : "f"(x));
    float hf = __uint_as_float(hb);
    float lf = x - hf;
    uint32_t lb;
    asm("cvt.rna.tf32.f32 %0, %1;" : "=r"(lb) : "f"(lf));
    h = hb; l = lb;
}

#define MMA_TF32(Cv, Af, Bf)                                                     \
    asm volatile("mma.sync.aligned.m16n8k8.row.col.f32.tf32.tf32.f32 "           \
                 "{%0,%1,%2,%3},{%4,%5,%6,%7},{%8,%9},{%0,%1,%2,%3};"            \
                 : "+f"(Cv[0]), "+f"(Cv[1]), "+f"(Cv[2]), "+f"(Cv[3])            \
                 : "r"(Af[0]), "r"(Af[1]), "r"(Af[2]), "r"(Af[3]),               \
                   "r"(Bf[0]), "r"(Bf[1]));

// ---------------- transpose x: NCHW -> [ci][b*1024+p] ----------------
__global__ void k_transpose_x(const float* __restrict__ x) {
    int id = blockIdx.x * 256 + threadIdx.x;      // 32*128*1024 total
    float v = x[id];
    int p  = id & 1023;
    int ci = (id >> 10) & 127;
    int b  = id >> 17;
    g_xT[(size_t)ci * MTOT + b * HWP + p] = v;
}

// ---------------- im2col (T layout both sides), optional fused BN+ReLU ----------------
__global__ void k_im2col(const float* __restrict__ src, float* __restrict__ dst,
                         const float* __restrict__ aa, const float* __restrict__ cc,
                         int doAct) {
    int k  = blockIdx.y;               // ci*9 + r
    int ci = k / 9, r = k % 9;
    int dh = r / 3 - 1, dw = r % 3 - 1;
    int m  = blockIdx.x * 256 + threadIdx.x;
    int p  = m & 1023, b = m >> 10;
    int h  = (p >> 5) + dh, w = (p & 31) + dw;
    float v = 0.f;
    if ((unsigned)h < 32u && (unsigned)w < 32u) {
        v = src[(size_t)ci * MTOT + b * HWP + h * 32 + w];
        if (doAct) v = fmaxf(fmaf(aa[ci], v, cc[ci]), 0.f);
    }
    dst[(size_t)k * MTOT + m] = v;
}

// ---------------- tensor-core GEMM (3xTF32): C[n][m] = sum_k A[k][m]*B[n][k] ------
// EPI: 0 = bias, 1 = bias+relu, 2 = gate epilogue (sigmoid(acc+bias); blend ret/xf)
// Block tile 128(m) x 128(n) x 16(k). 8 warps: 2(m) x 4(n); warp tile 64x32.
static constexpr int SMS = 136;   // padded smem row stride (conflict-free frag loads)

template <int EPI>
__global__ void __launch_bounds__(256)
k_gemm_tc(const float* __restrict__ A, const float* __restrict__ Bw,
          const float* __restrict__ bias, float* __restrict__ C, int K,
          const float* __restrict__ e_xf, const float* __restrict__ e_ret) {
    __shared__ uint32_t Ah[16][SMS], Al[16][SMS], Bh[16][SMS], Bl[16][SMS];
    int tid = threadIdx.x;
    int m0 = blockIdx.x * 128, n0 = blockIdx.y * 128;
    int wid = tid >> 5, lane = tid & 31;
    int wm = (wid & 1) * 64;          // warp m offset
    int wn = (wid >> 1) * 32;         // warp n offset
    int gid = lane >> 2, tig = lane & 3;

    float c[4][4][4];                 // [m-sub][n-sub][frag]
#pragma unroll
    for (int i = 0; i < 4; i++)
#pragma unroll
        for (int j = 0; j < 4; j++)
#pragma unroll
            for (int r = 0; r < 4; r++) c[i][j][r] = 0.f;

    int am = (tid & 31) * 4, ak = tid >> 5;    // A loader
    int bn = tid & 127, bk4 = (tid >> 7) * 4;  // B loader

    for (int k0 = 0; k0 < K; k0 += 16) {
        // ---- load A tile (hi/lo split), STS.128 ----
#pragma unroll
        for (int s = 0; s < 2; s++) {
            int kk = ak + s * 8;
            float4 v = *(const float4*)&A[(size_t)(k0 + kk) * MTOT + m0 + am];
            uint4 h, l;
            cvt_hilo(v.x, h.x, l.x); cvt_hilo(v.y, h.y, l.y);
            cvt_hilo(v.z, h.z, l.z); cvt_hilo(v.w, h.w, l.w);
            *(uint4*)&Ah[kk][am] = h;
            *(uint4*)&Al[kk][am] = l;
        }
        // ---- load B tile transposed (hi/lo split) ----
#pragma unroll
        for (int s = 0; s < 2; s++) {
            int kq = bk4 + s * 8;
            float4 v = *(const float4*)&Bw[(size_t)(n0 + bn) * K + k0 + kq];
            uint32_t h, l;
            cvt_hilo(v.x, h, l); Bh[kq + 0][bn] = h; Bl[kq + 0][bn] = l;
            cvt_hilo(v.y, h, l); Bh[kq + 1][bn] = h; Bl[kq + 1][bn] = l;
            cvt_hilo(v.z, h, l); Bh[kq + 2][bn] = h; Bl[kq + 2][bn] = l;
            cvt_hilo(v.w, h, l); Bh[kq + 3][bn] = h; Bl[kq + 3][bn] = l;
        }
        __syncthreads();

#pragma unroll
        for (int ks = 0; ks < 2; ks++) {
            int kb = ks * 8;
            uint32_t bfh[4][2], bfl[4][2];
#pragma unroll
            for (int j = 0; j < 4; j++) {
                int nc = wn + j * 8 + gid;
                bfh[j][0] = Bh[kb + tig][nc];
                bfh[j][1] = Bh[kb + tig + 4][nc];
                bfl[j][0] = Bl[kb + tig][nc];
                bfl[j][1] = Bl[kb + tig + 4][nc];
            }
#pragma unroll
            for (int i = 0; i < 4; i++) {
                int mr = wm + i * 16;
                uint32_t afh[4], afl[4];
                afh[0] = Ah[kb + tig][mr + gid];
                afh[1] = Ah[kb + tig][mr + gid + 8];
                afh[2] = Ah[kb + tig + 4][mr + gid];
                afh[3] = Ah[kb + tig + 4][mr + gid + 8];
                afl[0] = Al[kb + tig][mr + gid];
                afl[1] = Al[kb + tig][mr + gid + 8];
                afl[2] = Al[kb + tig + 4][mr + gid];
                afl[3] = Al[kb + tig + 4][mr + gid + 8];
#pragma unroll
                for (int j = 0; j < 4; j++) {
                    MMA_TF32(c[i][j], afh, bfh[j]);
                    MMA_TF32(c[i][j], afh, bfl[j]);
                    MMA_TF32(c[i][j], afl, bfh[j]);
                }
            }
        }
        __syncthreads();
    }

    // ---- epilogue ----
#pragma unroll
    for (int i = 0; i < 4; i++) {
        int mlo = m0 + wm + i * 16 + gid;
#pragma unroll
        for (int j = 0; j < 4; j++) {
            int nlo = n0 + wn + j * 8 + 2 * tig;
            float b0 = bias ? bias[nlo] : 0.f;
            float b1 = bias ? bias[nlo + 1] : 0.f;
#pragma unroll
            for (int r = 0; r < 4; r++) {
                int n = nlo + (r & 1);
                int m = mlo + (r >> 1) * 8;
                float v = c[i][j][r] + ((r & 1) ? b1 : b0);
                if (EPI == 1) v = fmaxf(v, 0.f);
                if (EPI == 2) {
                    float g = 1.f / (1.f + expf(-v));
                    size_t off = (size_t)n * MTOT + m;
                    v = g * e_ret[off] + (1.f - g) * e_xf[off];
                }
                C[(size_t)n * MTOT + m] = v;
            }
        }
    }
}

// ---------------- per-(c,b) reduction: sum, sumsq, max, min over 1024 ----------------
__global__ void __launch_bounds__(256) k_reduce_bc(const float* __restrict__ src,
                                                   float4* __restrict__ out) {
    int cb = blockIdx.x;
    const float* p = src + (size_t)cb * HWP;
    int tid = threadIdx.x;
    float v0 = p[tid], v1 = p[tid + 256], v2 = p[tid + 512], v3 = p[tid + 768];
    float s  = v0 + v1 + v2 + v3;
    float ss = v0 * v0 + v1 * v1 + v2 * v2 + v3 * v3;
    float mx = fmaxf(fmaxf(v0, v1), fmaxf(v2, v3));
    float mn = fminf(fminf(v0, v1), fminf(v2, v3));
#pragma unroll
    for (int o = 16; o; o >>= 1) {
        s  += __shfl_down_sync(0xffffffffu, s, o);
        ss += __shfl_down_sync(0xffffffffu, ss, o);
        mx = fmaxf(mx, __shfl_down_sync(0xffffffffu, mx, o));
        mn = fminf(mn, __shfl_down_sync(0xffffffffu, mn, o));
    }
    __shared__ float4 wred[8];
    int lane = tid & 31, wid = tid >> 5;
    if (lane == 0) wred[wid] = make_float4(s, ss, mx, mn);
    __syncthreads();
    if (tid == 0) {
        float4 r = wred[0];
        for (int i = 1; i < 8; i++) {
            r.x += wred[i].x; r.y += wred[i].y;
            r.z = fmaxf(r.z, wred[i].z); r.w = fminf(r.w, wred[i].w);
        }
        out[cb] = r;
    }
}

// ---------------- finalize BN coefficients per channel ----------------
__global__ void k_bn_coeffs(const float4* __restrict__ stats,
                            const float* __restrict__ g, const float* __restrict__ beta,
                            float* __restrict__ a, float* __restrict__ c) {
    int ch = threadIdx.x;     // <<<1,256>>>
    float s = 0.f, ss = 0.f;
    for (int b = 0; b < BB; b++) { float4 v = stats[ch * BB + b]; s += v.x; ss += v.y; }
    float mean = s * (1.f / 32768.f);
    float var  = ss * (1.f / 32768.f) - mean * mean;
    float av = g[ch] * rsqrtf(var + 1e-5f);
    a[ch] = av;
    c[ch] = beta[ch] - av * mean;
}

// ---------------- channel attention MLP ----------------
__global__ void __launch_bounds__(256) k_ca_mlp(const float* __restrict__ w1,
                                                const float* __restrict__ w2) {
    int b = blockIdx.x, tid = threadIdx.x;
    __shared__ float va[CO], vm[CO], hsum[16];
    {
        float4 st = g_stats2[tid * BB + b];
        float a = g_a2[tid], c = g_c2[tid];
        va[tid] = a * st.x * (1.f / 1024.f) + c;
        vm[tid] = (a >= 0.f ? a * st.z : a * st.w) + c;
    }
    __syncthreads();
    int wid = tid >> 5, lane = tid & 31;
    for (int u = 0; u < 2; u++) {
        int j = wid * 2 + u;
        float sa = 0.f, sm = 0.f;
        for (int c = lane; c < CO; c += 32) {
            float wv = w1[j * CO + c];
            sa += wv * va[c]; sm += wv * vm[c];
        }
#pragma unroll
        for (int o = 16; o; o >>= 1) {
            sa += __shfl_down_sync(0xffffffffu, sa, o);
            sm += __shfl_down_sync(0xffffffffu, sm, o);
        }
        if (lane == 0) hsum[j] = fmaxf(sa, 0.f) + fmaxf(sm, 0.f);
    }
    __syncthreads();
    float s = 0.f;
    for (int j = 0; j < 16; j++) s += hsum[j] * w2[tid * 16 + j];
    g_chatt[b * CO + tid] = 1.f / (1.f + expf(-s));
}

// ---------------- spatial pooling over channels (mean & max) ----------------
__global__ void __launch_bounds__(256) k_sp_pool() {
    int m = blockIdx.x * 256 + threadIdx.x;
    int b = m >> 10;
    __shared__ float co[CO], of[CO];
    {
        int t = threadIdx.x;
        float ca = g_chatt[b * CO + t];
        co[t] = ca * g_a2[t];
        of[t] = ca * g_c2[t];
    }
    __syncthreads();
    float s = 0.f, mx = -1e30f;
    for (int c = 0; c < CO; c++) {
        float v = fmaf(co[c], g_t2[(size_t)c * MTOT + m], of[c]);
        s += v; mx = fmaxf(mx, v);
    }
    g_spmean[m] = s * (1.f / 256.f);
    g_spmax[m]  = mx;
}

// ---------------- spatial attention 7x7 conv + sigmoid ----------------
__global__ void __launch_bounds__(1024) k_sa_conv(const float* __restrict__ sw,
                                                  const float* __restrict__ sb) {
    int b = blockIdx.x, p = threadIdx.x;
    __shared__ float me[HWP], ma[HWP];
    me[p] = g_spmean[b * HWP + p];
    ma[p] = g_spmax[b * HWP + p];
    __syncthreads();
    int h = p >> 5, w = p & 31;
    float acc = sb[0];
#pragma unroll
    for (int kh = 0; kh < 7; kh++) {
        int hh = h + kh - 3;
        if ((unsigned)hh >= 32u) continue;
#pragma unroll
        for (int kw = 0; kw < 7; kw++) {
            int ww = w + kw - 3;
            if ((unsigned)ww >= 32u) continue;
            int q = hh * 32 + ww;
            acc += sw[kh * 7 + kw] * me[q] + sw[49 + kh * 7 + kw] * ma[q];
        }
    }
    g_sa[b * HWP + p] = 1.f / (1.f + expf(-acc));
}

// ---------------- build xf (post channel+spatial attention), T layout ----------------
__global__ void k_build_xf() {
    int c = blockIdx.y;
    int m = blockIdx.x * 256 + threadIdx.x;
    int b = m >> 10;
    float ca = g_chatt[b * CO + c];
    float v = ca * fmaf(g_a2[c], g_t2[(size_t)c * MTOT + m], g_c2[c]) * g_sa[m];
    g_xfret[(size_t)c * MTOT + m] = v;
}

// ---------------- mem transpose [64][256] -> [256][64] ----------------
__global__ void k_mem_t(const float* __restrict__ mem) {
    int id = blockIdx.x * 256 + threadIdx.x;   // 16384
    int j = id >> 8, n = id & 255;
    g_memT[n * MEMN + j] = mem[id];
}

// ---------------- logits + softmax (rows of 64), writes attnT [64][M] ----------------
__global__ void __launch_bounds__(256) k_logits_softmax(const float* __restrict__ keys) {
    __shared__ float qs[16][128];
    __shared__ float ks[16][64];
    __shared__ float red[128][8];
    __shared__ float rowred[128];
    int tid = threadIdx.x;
    int m0 = blockIdx.x * 128;
    float acc[4][8];
#pragma unroll
    for (int i = 0; i < 4; i++)
#pragma unroll
        for (int j = 0; j < 8; j++) acc[i][j] = 0.f;
    int m4 = tid & 31, kr = tid >> 5;
    int jb = tid & 63, kq = tid >> 6;
    int tx = tid & 7, ty = tid >> 3;
    for (int k0 = 0; k0 < 256; k0 += 16) {
#pragma unroll
        for (int s = 0; s < 2; s++) {
            int kk = kr + s * 8;
            *(float4*)&qs[kk][m4 * 4] =
                *(const float4*)&g_q[(size_t)(k0 + kk) * MTOT + m0 + m4 * 4];
        }
        {
            float4 v = *(const float4*)&keys[jb * 256 + k0 + kq * 4];
            ks[kq * 4 + 0][jb] = v.x; ks[kq * 4 + 1][jb] = v.y;
            ks[kq * 4 + 2][jb] = v.z; ks[kq * 4 + 3][jb] = v.w;
        }
        __syncthreads();
#pragma unroll
        for (int kk = 0; kk < 16; kk++) {
            float a[4], b[8];
#pragma unroll
            for (int i = 0; i < 4; i++) a[i] = qs[kk][ty * 4 + i];
#pragma unroll
            for (int j = 0; j < 8; j++) b[j] = ks[kk][tx * 8 + j];
#pragma unroll
            for (int i = 0; i < 4; i++)
#pragma unroll
                for (int j = 0; j < 8; j++) acc[i][j] = fmaf(a[i], b[j], acc[i][j]);
        }
        __syncthreads();
    }
    const float sc = 0.0625f;   // 1/sqrt(256)
#pragma unroll
    for (int i = 0; i < 4; i++) {
        float mx = -1e30f;
#pragma unroll
        for (int j = 0; j < 8; j++) { acc[i][j] *= sc; mx = fmaxf(mx, acc[i][j]); }
        red[ty * 4 + i][tx] = mx;
    }
    __syncthreads();
    if (tid < 128) {
        float mx = -1e30f;
        for (int t = 0; t < 8; t++) mx = fmaxf(mx, red[tid][t]);
        rowred[tid] = mx;
    }
    __syncthreads();
#pragma unroll
    for (int i = 0; i < 4; i++) {
        float rm = rowred[ty * 4 + i], s = 0.f;
#pragma unroll
        for (int j = 0; j < 8; j++) { acc[i][j] = expf(acc[i][j] - rm); s += acc[i][j]; }
        red[ty * 4 + i][tx] = s;
    }
    __syncthreads();
    if (tid < 128) {
        float s = 0.f;
        for (int t = 0; t < 8; t++) s += red[tid][t];
        rowred[tid] = 1.f / s;
    }
    __syncthreads();
#pragma unroll
    for (int i = 0; i < 4; i++) {
        float inv = rowred[ty * 4 + i];
#pragma unroll
        for (int j = 0; j < 8; j++)
            g_attn[(size_t)(tx * 8 + j) * MTOT + m0 + ty * 4 + i] = acc[i][j] * inv;
    }
}

// ---------------- final: spike + BN(shortcut) + relu, write NCHW ----------------
__global__ void k_final(float* __restrict__ out) {
    int c = blockIdx.y;
    int m = blockIdx.x * 256 + threadIdx.x;
    float mo = g_mo[(size_t)c * MTOT + m];
    float spike = (0.1f * mo >= 1.0f) ? 1.f : 0.f;
    float idv = fmaf(g_asc[c], g_id[(size_t)c * MTOT + m], g_csc[c]);
    int b = m >> 10, p = m & 1023;
    out[(size_t)b * CO * HWP + c * HWP + p] = fmaxf(spike + idv, 0.f);
}

// =============================== host launcher ===============================
extern "C" void kernel_launch(void* const* d_in, const int* in_sizes, int n_in,
                              void* d_out, int out_size) {
    const float* x       = (const float*)d_in[0];
    const float* conv1_w = (const float*)d_in[1];
    const float* conv1_b = (const float*)d_in[2];
    const float* bn1_g   = (const float*)d_in[3];
    const float* bn1_b   = (const float*)d_in[4];
    const float* conv2_w = (const float*)d_in[5];
    const float* conv2_b = (const float*)d_in[6];
    const float* bn2_g   = (const float*)d_in[7];
    const float* bn2_b   = (const float*)d_in[8];
    const float* ca_w1   = (const float*)d_in[9];
    const float* ca_w2   = (const float*)d_in[10];
    const float* sa_w    = (const float*)d_in[11];
    const float* sa_b    = (const float*)d_in[12];
    const float* memp    = (const float*)d_in[13];
    const float* mem_keys= (const float*)d_in[14];
    const float* ctrl_w1 = (const float*)d_in[15];
    const float* ctrl_b1 = (const float*)d_in[16];
    const float* ctrl_w2 = (const float*)d_in[17];
    const float* ctrl_b2 = (const float*)d_in[18];
    const float* gate_w  = (const float*)d_in[19];
    const float* gate_b  = (const float*)d_in[20];
    const float* sc_w    = (const float*)d_in[21];
    const float* sc_g    = (const float*)d_in[22];
    const float* sc_b    = (const float*)d_in[23];

    float *xT, *col, *t1, *t2, *idb, *hb, *qb, *xfret, *attn, *mo, *memT;
    float *a1, *c1, *a2, *c2, *asc, *csc;
    float4 *st1, *st2, *stid;
    cudaGetSymbolAddress((void**)&xT, g_xT);
    cudaGetSymbolAddress((void**)&col, g_col);
    cudaGetSymbolAddress((void**)&t1, g_t1);
    cudaGetSymbolAddress((void**)&t2, g_t2);
    cudaGetSymbolAddress((void**)&idb, g_id);
    cudaGetSymbolAddress((void**)&hb, g_h);
    cudaGetSymbolAddress((void**)&qb, g_q);
    cudaGetSymbolAddress((void**)&xfret, g_xfret);
    cudaGetSymbolAddress((void**)&attn, g_attn);
    cudaGetSymbolAddress((void**)&mo, g_mo);
    cudaGetSymbolAddress((void**)&memT, g_memT);
    cudaGetSymbolAddress((void**)&a1, g_a1);
    cudaGetSymbolAddress((void**)&c1, g_c1);
    cudaGetSymbolAddress((void**)&a2, g_a2);
    cudaGetSymbolAddress((void**)&c2, g_c2);
    cudaGetSymbolAddress((void**)&asc, g_asc);
    cudaGetSymbolAddress((void**)&csc, g_csc);
    cudaGetSymbolAddress((void**)&st1, g_stats1);
    cudaGetSymbolAddress((void**)&st2, g_stats2);
    cudaGetSymbolAddress((void**)&stid, g_statsid);

    dim3 gemm_grid(MTOT / 128, 2);   // N = 256 always

    // 1) transpose input
    k_transpose_x<<<BB * CINN * HWP / 256, 256>>>(x);

    // 2) shortcut conv (1x1): plain GEMM K=128
    k_gemm_tc<0><<<gemm_grid, 256>>>(xT, sc_w, nullptr, idb, 128, nullptr, nullptr);
    k_reduce_bc<<<CO * BB, 256>>>(idb, stid);
    k_bn_coeffs<<<1, 256>>>(stid, sc_g, sc_b, asc, csc);

    // 3) conv1 = im2col + GEMM (K=1152)
    k_im2col<<<dim3(MTOT / 256, CINN * 9), 256>>>(xT, col, nullptr, nullptr, 0);
    k_gemm_tc<0><<<gemm_grid, 256>>>(col, conv1_w, conv1_b, t1, CINN * 9, nullptr, nullptr);
    k_reduce_bc<<<CO * BB, 256>>>(t1, st1);
    k_bn_coeffs<<<1, 256>>>(st1, bn1_g, bn1_b, a1, c1);

    // 4) conv2 = im2col (fused BN1+relu) + GEMM (K=2304)
    k_im2col<<<dim3(MTOT / 256, CO * 9), 256>>>(t1, col, a1, c1, 1);
    k_gemm_tc<0><<<gemm_grid, 256>>>(col, conv2_w, conv2_b, t2, CO * 9, nullptr, nullptr);
    k_reduce_bc<<<CO * BB, 256>>>(t2, st2);
    k_bn_coeffs<<<1, 256>>>(st2, bn2_g, bn2_b, a2, c2);

    // 5) channel attention (uses per-(b,c) stats of t2)
    k_ca_mlp<<<BB, 256>>>(ca_w1, ca_w2);

    // 6) spatial attention
    k_sp_pool<<<MTOT / 256, 256>>>();
    k_sa_conv<<<BB, 1024>>>(sa_w, sa_b);

    // 7) xf (attention-applied features) into front half of xfret buffer
    k_build_xf<<<dim3(MTOT / 256, CO), 256>>>();

    // 8) memory module
    k_gemm_tc<1><<<gemm_grid, 256>>>(xfret, ctrl_w1, ctrl_b1, hb, 256, nullptr, nullptr);
    k_gemm_tc<0><<<gemm_grid, 256>>>(hb, ctrl_w2, ctrl_b2, qb, 256, nullptr, nullptr);
    k_mem_t<<<MEMN * CO / 256, 256>>>(memp);
    k_logits_softmax<<<MTOT / 128, 256>>>(mem_keys);
    k_gemm_tc<0><<<gemm_grid, 256>>>(attn, memT, nullptr, xfret + (size_t)256 * MTOT,
                                     MEMN, nullptr, nullptr);
    k_gemm_tc<2><<<gemm_grid, 256>>>(xfret, gate_w, gate_b, mo, 512,
                                     xfret, xfret + (size_t)256 * MTOT);

    // 9) spike + shortcut + relu -> NCHW output
    k_final<<<dim3(MTOT / 256, CO), 256>>>((float*)d_out);
}

// round 8
// speedup vs baseline: 1.3820x; 1.0691x over previous
#include <cuda_runtime.h>
#include <math.h>
#include <stdint.h>

#define CDIV(a,b) (((a)+(b)-1)/(b))

static constexpr int BB   = 32;
static constexpr int CINN = 128;
static constexpr int CO   = 256;
static constexpr int HWP  = 1024;          // 32*32
static constexpr int MTOT = BB * HWP;      // 32768
static constexpr int MEMN = 64;

// ---------------- scratch (static device memory; no allocations) ----------------
__device__ float g_xT   [(size_t)CINN * MTOT];        // x transposed  [128][M]
__device__ float g_t1   [(size_t)CO * MTOT];          // conv1 raw     [256][M]
__device__ float g_t2   [(size_t)CO * MTOT];          // conv2 raw
__device__ float g_id   [(size_t)CO * MTOT];          // shortcut conv raw
__device__ float g_h    [(size_t)CO * MTOT];          // ctrl hidden
__device__ float g_q    [(size_t)CO * MTOT];          // ctrl out (query)
__device__ float g_xfret[(size_t)512 * MTOT];         // [xfT(256) ; retT(256)][M]
__device__ float g_attn [(size_t)MEMN * MTOT];        // attn transposed [64][M]
__device__ float g_mo   [(size_t)CO * MTOT];          // memory out
__device__ float g_memT [CO * MEMN];                  // mem transposed [256][64]
__device__ float4 g_stats1 [CO * BB];
__device__ float4 g_stats2 [CO * BB];
__device__ float4 g_statsid[CO * BB];
__device__ float g_a1[CO], g_c1[CO], g_a2[CO], g_c2[CO], g_asc[CO], g_csc[CO];
__device__ float g_chatt[BB * CO];
__device__ float g_spmean[MTOT], g_spmax[MTOT], g_sa[MTOT];

// ---------------- tf32 helpers ----------------
__device__ __forceinline__ void cvt_hilo(float x, uint32_t& h, uint32_t& l) {
    uint32_t hb;
    asm("cvt.rna.tf32.f32 %0, %1;" : "=r"(hb) : "f"(x));
    float hf = __uint_as_float(hb);
    float lf = x - hf;
    uint32_t lb;
    asm("cvt.rna.tf32.f32 %0, %1;" : "=r"(lb) : "f"(lf));
    h = hb; l = lb;
}

#define MMA_TF32(Cv, Af, Bf)                                                     \
    asm volatile("mma.sync.aligned.m16n8k8.row.col.f32.tf32.tf32.f32 "           \
                 "{%0,%1,%2,%3},{%4,%5,%6,%7},{%8,%9},{%0,%1,%2,%3};"            \
                 : "+f"(Cv[0]), "+f"(Cv[1]), "+f"(Cv[2]), "+f"(Cv[3])            \
                 : "r"(Af[0]), "r"(Af[1]), "r"(Af[2]), "r"(Af[3]),               \
                   "r"(Bf[0]), "r"(Bf[1]));

// ---------------- transpose x: NCHW -> [ci][b*1024+p] ----------------
__global__ void k_transpose_x(const float* __restrict__ x) {
    int id = blockIdx.x * 256 + threadIdx.x;      // 32*128*1024 total
    float v = x[id];
    int p  = id & 1023;
    int ci = (id >> 10) & 127;
    int b  = id >> 17;
    g_xT[(size_t)ci * MTOT + b * HWP + p] = v;
}

static constexpr int SMS = 136;   // padded smem row stride (conflict-free frag loads)

// ======================= shared GEMM core (mma part) =========================
// Block tile 128(m) x 128(n) x 16(k). 8 warps: 2(m) x 4(n); warp tile 64x32.
// Smem tiles Ah/Al/Bh/Bl must be filled by the caller-specific loader.

__device__ __forceinline__ void mma_block(
    uint32_t (&Ah)[16][SMS], uint32_t (&Al)[16][SMS],
    uint32_t (&Bh)[16][SMS], uint32_t (&Bl)[16][SMS],
    int wm, int wn, int gid, int tig, float (&c)[4][4][4]) {
#pragma unroll
    for (int ks = 0; ks < 2; ks++) {
        int kb = ks * 8;
        uint32_t bfh[4][2], bfl[4][2];
#pragma unroll
        for (int j = 0; j < 4; j++) {
            int nc = wn + j * 8 + gid;
            bfh[j][0] = Bh[kb + tig][nc];
            bfh[j][1] = Bh[kb + tig + 4][nc];
            bfl[j][0] = Bl[kb + tig][nc];
            bfl[j][1] = Bl[kb + tig + 4][nc];
        }
#pragma unroll
        for (int i = 0; i < 4; i++) {
            int mr = wm + i * 16;
            uint32_t afh[4], afl[4];
            afh[0] = Ah[kb + tig][mr + gid];
            afh[1] = Ah[kb + tig][mr + gid + 8];
            afh[2] = Ah[kb + tig + 4][mr + gid];
            afh[3] = Ah[kb + tig + 4][mr + gid + 8];
            afl[0] = Al[kb + tig][mr + gid];
            afl[1] = Al[kb + tig][mr + gid + 8];
            afl[2] = Al[kb + tig + 4][mr + gid];
            afl[3] = Al[kb + tig + 4][mr + gid + 8];
#pragma unroll
            for (int j = 0; j < 4; j++) {
                MMA_TF32(c[i][j], afh, bfh[j]);
                MMA_TF32(c[i][j], afh, bfl[j]);
                MMA_TF32(c[i][j], afl, bfh[j]);
            }
        }
    }
}

// ---------------- tensor-core GEMM (3xTF32): C[n][m] = sum_k A[k][m]*B[n][k] ------
// EPI: 0 = bias, 1 = bias+relu, 2 = gate epilogue (sigmoid(acc+bias); blend ret/xf)
template <int EPI>
__global__ void __launch_bounds__(256)
k_gemm_tc(const float* __restrict__ A, const float* __restrict__ Bw,
          const float* __restrict__ bias, float* __restrict__ C, int K,
          const float* __restrict__ e_xf, const float* __restrict__ e_ret) {
    __shared__ uint32_t Ah[16][SMS], Al[16][SMS], Bh[16][SMS], Bl[16][SMS];
    int tid = threadIdx.x;
    int m0 = blockIdx.x * 128, n0 = blockIdx.y * 128;
    int wid = tid >> 5, lane = tid & 31;
    int wm = (wid & 1) * 64;
    int wn = (wid >> 1) * 32;
    int gid = lane >> 2, tig = lane & 3;

    float c[4][4][4];
#pragma unroll
    for (int i = 0; i < 4; i++)
#pragma unroll
        for (int j = 0; j < 4; j++)
#pragma unroll
            for (int r = 0; r < 4; r++) c[i][j][r] = 0.f;

    int am = (tid & 31) * 4, ak = tid >> 5;    // A loader
    int bn = tid & 127, bk4 = (tid >> 7) * 4;  // B loader

    for (int k0 = 0; k0 < K; k0 += 16) {
#pragma unroll
        for (int s = 0; s < 2; s++) {
            int kk = ak + s * 8;
            float4 v = *(const float4*)&A[(size_t)(k0 + kk) * MTOT + m0 + am];
            uint4 h, l;
            cvt_hilo(v.x, h.x, l.x); cvt_hilo(v.y, h.y, l.y);
            cvt_hilo(v.z, h.z, l.z); cvt_hilo(v.w, h.w, l.w);
            *(uint4*)&Ah[kk][am] = h;
            *(uint4*)&Al[kk][am] = l;
        }
#pragma unroll
        for (int s = 0; s < 2; s++) {
            int kq = bk4 + s * 8;
            float4 v = *(const float4*)&Bw[(size_t)(n0 + bn) * K + k0 + kq];
            uint32_t h, l;
            cvt_hilo(v.x, h, l); Bh[kq + 0][bn] = h; Bl[kq + 0][bn] = l;
            cvt_hilo(v.y, h, l); Bh[kq + 1][bn] = h; Bl[kq + 1][bn] = l;
            cvt_hilo(v.z, h, l); Bh[kq + 2][bn] = h; Bl[kq + 2][bn] = l;
            cvt_hilo(v.w, h, l); Bh[kq + 3][bn] = h; Bl[kq + 3][bn] = l;
        }
        __syncthreads();
        mma_block(Ah, Al, Bh, Bl, wm, wn, gid, tig, c);
        __syncthreads();
    }

#pragma unroll
    for (int i = 0; i < 4; i++) {
        int mlo = m0 + wm + i * 16 + gid;
#pragma unroll
        for (int j = 0; j < 4; j++) {
            int nlo = n0 + wn + j * 8 + 2 * tig;
            float b0 = bias ? bias[nlo] : 0.f;
            float b1 = bias ? bias[nlo + 1] : 0.f;
#pragma unroll
            for (int r = 0; r < 4; r++) {
                int n = nlo + (r & 1);
                int m = mlo + (r >> 1) * 8;
                float v = c[i][j][r] + ((r & 1) ? b1 : b0);
                if (EPI == 1) v = fmaxf(v, 0.f);
                if (EPI == 2) {
                    float g = 1.f / (1.f + expf(-v));
                    size_t off = (size_t)n * MTOT + m;
                    v = g * e_ret[off] + (1.f - g) * e_xf[off];
                }
                C[(size_t)n * MTOT + m] = v;
            }
        }
    }
}

// ---------------- implicit-GEMM conv (3x3, pad 1) on tensor cores ----------------
// A[k][m] gathered on the fly from src[ci][b*1024 + (h+dh)*32 + (w+dw)] with
// zero padding; k = ci*9 + (dh+1)*3 + (dw+1). ACT=1: fuse BN+ReLU of src.
template <int ACT>
__global__ void __launch_bounds__(256)
k_conv_tc(const float* __restrict__ src, const float* __restrict__ Bw,
          const float* __restrict__ bias, float* __restrict__ C, int K,
          const float* __restrict__ aa, const float* __restrict__ cc) {
    __shared__ uint32_t Ah[16][SMS], Al[16][SMS], Bh[16][SMS], Bl[16][SMS];
    int tid = threadIdx.x;
    int m0 = blockIdx.x * 128, n0 = blockIdx.y * 128;
    int wid = tid >> 5, lane = tid & 31;
    int wm = (wid & 1) * 64;
    int wn = (wid >> 1) * 32;
    int gid = lane >> 2, tig = lane & 3;

    float c[4][4][4];
#pragma unroll
    for (int i = 0; i < 4; i++)
#pragma unroll
        for (int j = 0; j < 4; j++)
#pragma unroll
            for (int r = 0; r < 4; r++) c[i][j][r] = 0.f;

    int am = (tid & 31) * 4, ak = tid >> 5;    // A loader: thread owns (kk, m-range of 4)
    int bn = tid & 127, bk4 = (tid >> 7) * 4;  // B loader

    // per-thread invariants for the gather
    int pm = (m0 + am) & 1023;                 // position within image (batch-invariant)
    int hbase = pm >> 5, wbase = pm & 31;

    for (int k0 = 0; k0 < K; k0 += 16) {
        // ---- implicit im2col A tile ----
#pragma unroll
        for (int s = 0; s < 2; s++) {
            int kk = ak + s * 8;
            int k  = k0 + kk;
            int ci = k / 9, r = k - ci * 9;
            int dh = r / 3 - 1, dw = r - (r / 3) * 3 - 1;
            int h  = hbase + dh;
            bool hok = (unsigned)h < 32u;
            const float* sp = src + (size_t)ci * MTOT + (m0 + am) + dh * 32 + dw;
            float v[4];
#pragma unroll
            for (int e = 0; e < 4; e++) {
                int w = wbase + dw + e;
                v[e] = (hok && (unsigned)w < 32u) ? __ldg(sp + e) : 0.f;
            }
            if (ACT) {
                float a = aa[ci], cbv = cc[ci];
#pragma unroll
                for (int e = 0; e < 4; e++) v[e] = fmaxf(fmaf(a, v[e], cbv), 0.f);
            }
            uint4 hbits, lbits;
            cvt_hilo(v[0], hbits.x, lbits.x); cvt_hilo(v[1], hbits.y, lbits.y);
            cvt_hilo(v[2], hbits.z, lbits.z); cvt_hilo(v[3], hbits.w, lbits.w);
            *(uint4*)&Ah[kk][am] = hbits;
            *(uint4*)&Al[kk][am] = lbits;
        }
        // ---- B tile (weights, [n][K]) ----
#pragma unroll
        for (int s = 0; s < 2; s++) {
            int kq = bk4 + s * 8;
            float4 v = *(const float4*)&Bw[(size_t)(n0 + bn) * K + k0 + kq];
            uint32_t h, l;
            cvt_hilo(v.x, h, l); Bh[kq + 0][bn] = h; Bl[kq + 0][bn] = l;
            cvt_hilo(v.y, h, l); Bh[kq + 1][bn] = h; Bl[kq + 1][bn] = l;
            cvt_hilo(v.z, h, l); Bh[kq + 2][bn] = h; Bl[kq + 2][bn] = l;
            cvt_hilo(v.w, h, l); Bh[kq + 3][bn] = h; Bl[kq + 3][bn] = l;
        }
        __syncthreads();
        mma_block(Ah, Al, Bh, Bl, wm, wn, gid, tig, c);
        __syncthreads();
    }

    // epilogue: bias only
#pragma unroll
    for (int i = 0; i < 4; i++) {
        int mlo = m0 + wm + i * 16 + gid;
#pragma unroll
        for (int j = 0; j < 4; j++) {
            int nlo = n0 + wn + j * 8 + 2 * tig;
            float b0 = bias[nlo], b1 = bias[nlo + 1];
#pragma unroll
            for (int r = 0; r < 4; r++) {
                int n = nlo + (r & 1);
                int m = mlo + (r >> 1) * 8;
                C[(size_t)n * MTOT + m] = c[i][j][r] + ((r & 1) ? b1 : b0);
            }
        }
    }
}

// ---------------- per-(c,b) reduction: sum, sumsq, max, min over 1024 ----------------
__global__ void __launch_bounds__(256) k_reduce_bc(const float* __restrict__ src,
                                                   float4* __restrict__ out) {
    int cb = blockIdx.x;
    const float* p = src + (size_t)cb * HWP;
    int tid = threadIdx.x;
    float v0 = p[tid], v1 = p[tid + 256], v2 = p[tid + 512], v3 = p[tid + 768];
    float s  = v0 + v1 + v2 + v3;
    float ss = v0 * v0 + v1 * v1 + v2 * v2 + v3 * v3;
    float mx = fmaxf(fmaxf(v0, v1), fmaxf(v2, v3));
    float mn = fminf(fminf(v0, v1), fminf(v2, v3));
#pragma unroll
    for (int o = 16; o; o >>= 1) {
        s  += __shfl_down_sync(0xffffffffu, s, o);
        ss += __shfl_down_sync(0xffffffffu, ss, o);
        mx = fmaxf(mx, __shfl_down_sync(0xffffffffu, mx, o));
        mn = fminf(mn, __shfl_down_sync(0xffffffffu, mn, o));
    }
    __shared__ float4 wred[8];
    int lane = tid & 31, wid = tid >> 5;
    if (lane == 0) wred[wid] = make_float4(s, ss, mx, mn);
    __syncthreads();
    if (tid == 0) {
        float4 r = wred[0];
        for (int i = 1; i < 8; i++) {
            r.x += wred[i].x; r.y += wred[i].y;
            r.z = fmaxf(r.z, wred[i].z); r.w = fminf(r.w, wred[i].w);
        }
        out[cb] = r;
    }
}

// ---------------- finalize BN coefficients per channel ----------------
__global__ void k_bn_coeffs(const float4* __restrict__ stats,
                            const float* __restrict__ g, const float* __restrict__ beta,
                            float* __restrict__ a, float* __restrict__ c) {
    int ch = threadIdx.x;     // <<<1,256>>>
    float s = 0.f, ss = 0.f;
    for (int b = 0; b < BB; b++) { float4 v = stats[ch * BB + b]; s += v.x; ss += v.y; }
    float mean = s * (1.f / 32768.f);
    float var  = ss * (1.f / 32768.f) - mean * mean;
    float av = g[ch] * rsqrtf(var + 1e-5f);
    a[ch] = av;
    c[ch] = beta[ch] - av * mean;
}

// ---------------- channel attention MLP ----------------
__global__ void __launch_bounds__(256) k_ca_mlp(const float* __restrict__ w1,
                                                const float* __restrict__ w2) {
    int b = blockIdx.x, tid = threadIdx.x;
    __shared__ float va[CO], vm[CO], hsum[16];
    {
        float4 st = g_stats2[tid * BB + b];
        float a = g_a2[tid], c = g_c2[tid];
        va[tid] = a * st.x * (1.f / 1024.f) + c;
        vm[tid] = (a >= 0.f ? a * st.z : a * st.w) + c;
    }
    __syncthreads();
    int wid = tid >> 5, lane = tid & 31;
    for (int u = 0; u < 2; u++) {
        int j = wid * 2 + u;
        float sa = 0.f, sm = 0.f;
        for (int c = lane; c < CO; c += 32) {
            float wv = w1[j * CO + c];
            sa += wv * va[c]; sm += wv * vm[c];
        }
#pragma unroll
        for (int o = 16; o; o >>= 1) {
            sa += __shfl_down_sync(0xffffffffu, sa, o);
            sm += __shfl_down_sync(0xffffffffu, sm, o);
        }
        if (lane == 0) hsum[j] = fmaxf(sa, 0.f) + fmaxf(sm, 0.f);
    }
    __syncthreads();
    float s = 0.f;
    for (int j = 0; j < 16; j++) s += hsum[j] * w2[tid * 16 + j];
    g_chatt[b * CO + tid] = 1.f / (1.f + expf(-s));
}

// ---------------- spatial pooling over channels (mean & max) ----------------
__global__ void __launch_bounds__(256) k_sp_pool() {
    int m = blockIdx.x * 256 + threadIdx.x;
    int b = m >> 10;
    __shared__ float co[CO], of[CO];
    {
        int t = threadIdx.x;
        float ca = g_chatt[b * CO + t];
        co[t] = ca * g_a2[t];
        of[t] = ca * g_c2[t];
    }
    __syncthreads();
    float s = 0.f, mx = -1e30f;
    for (int c = 0; c < CO; c++) {
        float v = fmaf(co[c], g_t2[(size_t)c * MTOT + m], of[c]);
        s += v; mx = fmaxf(mx, v);
    }
    g_spmean[m] = s * (1.f / 256.f);
    g_spmax[m]  = mx;
}

// ---------------- spatial attention 7x7 conv + sigmoid ----------------
__global__ void __launch_bounds__(1024) k_sa_conv(const float* __restrict__ sw,
                                                  const float* __restrict__ sb) {
    int b = blockIdx.x, p = threadIdx.x;
    __shared__ float me[HWP], ma[HWP];
    me[p] = g_spmean[b * HWP + p];
    ma[p] = g_spmax[b * HWP + p];
    __syncthreads();
    int h = p >> 5, w = p & 31;
    float acc = sb[0];
#pragma unroll
    for (int kh = 0; kh < 7; kh++) {
        int hh = h + kh - 3;
        if ((unsigned)hh >= 32u) continue;
#pragma unroll
        for (int kw = 0; kw < 7; kw++) {
            int ww = w + kw - 3;
            if ((unsigned)ww >= 32u) continue;
            int q = hh * 32 + ww;
            acc += sw[kh * 7 + kw] * me[q] + sw[49 + kh * 7 + kw] * ma[q];
        }
    }
    g_sa[b * HWP + p] = 1.f / (1.f + expf(-acc));
}

// ---------------- build xf (post channel+spatial attention), T layout ----------------
__global__ void k_build_xf() {
    int c = blockIdx.y;
    int m = blockIdx.x * 256 + threadIdx.x;
    int b = m >> 10;
    float ca = g_chatt[b * CO + c];
    float v = ca * fmaf(g_a2[c], g_t2[(size_t)c * MTOT + m], g_c2[c]) * g_sa[m];
    g_xfret[(size_t)c * MTOT + m] = v;
}

// ---------------- mem transpose [64][256] -> [256][64] ----------------
__global__ void k_mem_t(const float* __restrict__ mem) {
    int id = blockIdx.x * 256 + threadIdx.x;   // 16384
    int j = id >> 8, n = id & 255;
    g_memT[n * MEMN + j] = mem[id];
}

// ---------------- logits + softmax (rows of 64), writes attnT [64][M] ----------------
__global__ void __launch_bounds__(256) k_logits_softmax(const float* __restrict__ keys) {
    __shared__ float qs[16][128];
    __shared__ float ks[16][64];
    __shared__ float red[128][8];
    __shared__ float rowred[128];
    int tid = threadIdx.x;
    int m0 = blockIdx.x * 128;
    float acc[4][8];
#pragma unroll
    for (int i = 0; i < 4; i++)
#pragma unroll
        for (int j = 0; j < 8; j++) acc[i][j] = 0.f;
    int m4 = tid & 31, kr = tid >> 5;
    int jb = tid & 63, kq = tid >> 6;
    int tx = tid & 7, ty = tid >> 3;
    for (int k0 = 0; k0 < 256; k0 += 16) {
#pragma unroll
        for (int s = 0; s < 2; s++) {
            int kk = kr + s * 8;
            *(float4*)&qs[kk][m4 * 4] =
                *(const float4*)&g_q[(size_t)(k0 + kk) * MTOT + m0 + m4 * 4];
        }
        {
            float4 v = *(const float4*)&keys[jb * 256 + k0 + kq * 4];
            ks[kq * 4 + 0][jb] = v.x; ks[kq * 4 + 1][jb] = v.y;
            ks[kq * 4 + 2][jb] = v.z; ks[kq * 4 + 3][jb] = v.w;
        }
        __syncthreads();
#pragma unroll
        for (int kk = 0; kk < 16; kk++) {
            float a[4], b[8];
#pragma unroll
            for (int i = 0; i < 4; i++) a[i] = qs[kk][ty * 4 + i];
#pragma unroll
            for (int j = 0; j < 8; j++) b[j] = ks[kk][tx * 8 + j];
#pragma unroll
            for (int i = 0; i < 4; i++)
#pragma unroll
                for (int j = 0; j < 8; j++) acc[i][j] = fmaf(a[i], b[j], acc[i][j]);
        }
        __syncthreads();
    }
    const float sc = 0.0625f;   // 1/sqrt(256)
#pragma unroll
    for (int i = 0; i < 4; i++) {
        float mx = -1e30f;
#pragma unroll
        for (int j = 0; j < 8; j++) { acc[i][j] *= sc; mx = fmaxf(mx, acc[i][j]); }
        red[ty * 4 + i][tx] = mx;
    }
    __syncthreads();
    if (tid < 128) {
        float mx = -1e30f;
        for (int t = 0; t < 8; t++) mx = fmaxf(mx, red[tid][t]);
        rowred[tid] = mx;
    }
    __syncthreads();
#pragma unroll
    for (int i = 0; i < 4; i++) {
        float rm = rowred[ty * 4 + i], s = 0.f;
#pragma unroll
        for (int j = 0; j < 8; j++) { acc[i][j] = expf(acc[i][j] - rm); s += acc[i][j]; }
        red[ty * 4 + i][tx] = s;
    }
    __syncthreads();
    if (tid < 128) {
        float s = 0.f;
        for (int t = 0; t < 8; t++) s += red[tid][t];
        rowred[tid] = 1.f / s;
    }
    __syncthreads();
#pragma unroll
    for (int i = 0; i < 4; i++) {
        float inv = rowred[ty * 4 + i];
#pragma unroll
        for (int j = 0; j < 8; j++)
            g_attn[(size_t)(tx * 8 + j) * MTOT + m0 + ty * 4 + i] = acc[i][j] * inv;
    }
}

// ---------------- final: spike + BN(shortcut) + relu, write NCHW ----------------
__global__ void k_final(float* __restrict__ out) {
    int c = blockIdx.y;
    int m = blockIdx.x * 256 + threadIdx.x;
    float mo = g_mo[(size_t)c * MTOT + m];
    float spike = (0.1f * mo >= 1.0f) ? 1.f : 0.f;
    float idv = fmaf(g_asc[c], g_id[(size_t)c * MTOT + m], g_csc[c]);
    int b = m >> 10, p = m & 1023;
    out[(size_t)b * CO * HWP + c * HWP + p] = fmaxf(spike + idv, 0.f);
}

// =============================== host launcher ===============================
extern "C" void kernel_launch(void* const* d_in, const int* in_sizes, int n_in,
                              void* d_out, int out_size) {
    const float* x       = (const float*)d_in[0];
    const float* conv1_w = (const float*)d_in[1];
    const float* conv1_b = (const float*)d_in[2];
    const float* bn1_g   = (const float*)d_in[3];
    const float* bn1_b   = (const float*)d_in[4];
    const float* conv2_w = (const float*)d_in[5];
    const float* conv2_b = (const float*)d_in[6];
    const float* bn2_g   = (const float*)d_in[7];
    const float* bn2_b   = (const float*)d_in[8];
    const float* ca_w1   = (const float*)d_in[9];
    const float* ca_w2   = (const float*)d_in[10];
    const float* sa_w    = (const float*)d_in[11];
    const float* sa_b    = (const float*)d_in[12];
    const float* memp    = (const float*)d_in[13];
    const float* mem_keys= (const float*)d_in[14];
    const float* ctrl_w1 = (const float*)d_in[15];
    const float* ctrl_b1 = (const float*)d_in[16];
    const float* ctrl_w2 = (const float*)d_in[17];
    const float* ctrl_b2 = (const float*)d_in[18];
    const float* gate_w  = (const float*)d_in[19];
    const float* gate_b  = (const float*)d_in[20];
    const float* sc_w    = (const float*)d_in[21];
    const float* sc_g    = (const float*)d_in[22];
    const float* sc_b    = (const float*)d_in[23];

    float *xT, *t1, *t2, *idb, *hb, *qb, *xfret, *attn, *mo, *memT;
    float *a1, *c1, *a2, *c2, *asc, *csc;
    float4 *st1, *st2, *stid;
    cudaGetSymbolAddress((void**)&xT, g_xT);
    cudaGetSymbolAddress((void**)&t1, g_t1);
    cudaGetSymbolAddress((void**)&t2, g_t2);
    cudaGetSymbolAddress((void**)&idb, g_id);
    cudaGetSymbolAddress((void**)&hb, g_h);
    cudaGetSymbolAddress((void**)&qb, g_q);
    cudaGetSymbolAddress((void**)&xfret, g_xfret);
    cudaGetSymbolAddress((void**)&attn, g_attn);
    cudaGetSymbolAddress((void**)&mo, g_mo);
    cudaGetSymbolAddress((void**)&memT, g_memT);
    cudaGetSymbolAddress((void**)&a1, g_a1);
    cudaGetSymbolAddress((void**)&c1, g_c1);
    cudaGetSymbolAddress((void**)&a2, g_a2);
    cudaGetSymbolAddress((void**)&c2, g_c2);
    cudaGetSymbolAddress((void**)&asc, g_asc);
    cudaGetSymbolAddress((void**)&csc, g_csc);
    cudaGetSymbolAddress((void**)&st1, g_stats1);
    cudaGetSymbolAddress((void**)&st2, g_stats2);
    cudaGetSymbolAddress((void**)&stid, g_statsid);

    dim3 gemm_grid(MTOT / 128, 2);   // N = 256 always

    // 1) transpose input
    k_transpose_x<<<BB * CINN * HWP / 256, 256>>>(x);

    // 2) shortcut conv (1x1): plain GEMM K=128
    k_gemm_tc<0><<<gemm_grid, 256>>>(xT, sc_w, nullptr, idb, 128, nullptr, nullptr);
    k_reduce_bc<<<CO * BB, 256>>>(idb, stid);
    k_bn_coeffs<<<1, 256>>>(stid, sc_g, sc_b, asc, csc);

    // 3) conv1: implicit-GEMM (K=1152) straight from xT
    k_conv_tc<0><<<gemm_grid, 256>>>(xT, conv1_w, conv1_b, t1, CINN * 9,
                                     nullptr, nullptr);
    k_reduce_bc<<<CO * BB, 256>>>(t1, st1);
    k_bn_coeffs<<<1, 256>>>(st1, bn1_g, bn1_b, a1, c1);

    // 4) conv2: implicit-GEMM (K=2304) with fused BN1+ReLU in the gather
    k_conv_tc<1><<<gemm_grid, 256>>>(t1, conv2_w, conv2_b, t2, CO * 9, a1, c1);
    k_reduce_bc<<<CO * BB, 256>>>(t2, st2);
    k_bn_coeffs<<<1, 256>>>(st2, bn2_g, bn2_b, a2, c2);

    // 5) channel attention (uses per-(b,c) stats of t2)
    k_ca_mlp<<<BB, 256>>>(ca_w1, ca_w2);

    // 6) spatial attention
    k_sp_pool<<<MTOT / 256, 256>>>();
    k_sa_conv<<<BB, 1024>>>(sa_w, sa_b);

    // 7) xf (attention-applied features) into front half of xfret buffer
    k_build_xf<<<dim3(MTOT / 256, CO), 256>>>();

    // 8) memory module
    k_gemm_tc<1><<<gemm_grid, 256>>>(xfret, ctrl_w1, ctrl_b1, hb, 256, nullptr, nullptr);
    k_gemm_tc<0><<<gemm_grid, 256>>>(hb, ctrl_w2, ctrl_b2, qb, 256, nullptr, nullptr);
    k_mem_t<<<MEMN * CO / 256, 256>>>(memp);
    k_logits_softmax<<<MTOT / 128, 256>>>(mem_keys);
    k_gemm_tc<0><<<gemm_grid, 256>>>(attn, memT, nullptr, xfret + (size_t)256 * MTOT,
                                     MEMN, nullptr, nullptr);
    k_gemm_tc<2><<<gemm_grid, 256>>>(xfret, gate_w, gate_b, mo, 512,
                                     xfret, xfret + (size_t)256 * MTOT);

    // 9) spike + shortcut + relu -> NCHW output
    k_final<<<dim3(MTOT / 256, CO), 256>>>((float*)d_out);
}